// round 2
// baseline (speedup 1.0000x reference)
#include <cuda_runtime.h>
#include <math.h>

// B=4, N_TR=256, M_DET=1024, T=16, D=256, H=4, HD=64, N_FUSER=4, N_GNN=12, ITERS=100
#define P_TRK 16384
#define P_DET 4096
#define P_TR  1024
#define ZROW  263425  // 257*1025
#define NORM_C  (-7.1546153569136625f)  /* -ln(1280) */
#define LOG1024 6.931471805599453f
#define LOG256  5.545177444479562f
#define NBLK_SINK 148

__device__ float g_pool[54000000];

// ---------------------------------------------------------------------------
// Small GEMM (64x64 tile): out[o,p] = act(W@X + b + add). X2: rows >=256.
// ---------------------------------------------------------------------------
__global__ __launch_bounds__(256) void gemm_k(
    const float* __restrict__ W, const float* __restrict__ bias,
    const float* __restrict__ X, const float* __restrict__ X2,
    const float* __restrict__ addp, float* __restrict__ out,
    int I, int P, int relu)
{
    __shared__ float Ws[16][68];
    __shared__ float Xs[16][64];
    int tid = threadIdx.x;
    int tx = tid & 15, ty = tid >> 4;
    int pc = blockIdx.x * 64;
    int oc = blockIdx.y * 64;
    float acc[4][4] = {};
    for (int kc = 0; kc < I; kc += 16) {
#pragma unroll
        for (int r = 0; r < 4; r++) {
            int e = tid + r * 256;
            int ol = e >> 4, kl = e & 15;
            Ws[kl][ol] = W[(oc + ol) * I + kc + kl];
        }
#pragma unroll
        for (int r = 0; r < 4; r++) {
            int e = tid + r * 256;
            int kl = e >> 6, pl = e & 63;
            int gi = kc + kl;
            const float* src = (X2 != nullptr && gi >= 256) ? (X2 + (gi - 256) * P)
                                                            : (X + gi * P);
            Xs[kl][pl] = src[pc + pl];
        }
        __syncthreads();
#pragma unroll
        for (int kk = 0; kk < 16; kk++) {
            float a[4], b[4];
#pragma unroll
            for (int i = 0; i < 4; i++) a[i] = Ws[kk][ty * 4 + i];
#pragma unroll
            for (int j = 0; j < 4; j++) b[j] = Xs[kk][tx * 4 + j];
#pragma unroll
            for (int i = 0; i < 4; i++)
#pragma unroll
                for (int j = 0; j < 4; j++) acc[i][j] += a[i] * b[j];
        }
        __syncthreads();
    }
#pragma unroll
    for (int i = 0; i < 4; i++) {
        int o = oc + ty * 4 + i;
        float bv = bias ? bias[o] : 0.f;
#pragma unroll
        for (int j = 0; j < 4; j++) {
            int p = pc + tx * 4 + j;
            float v = acc[i][j] + bv;
            if (addp) v += addp[o * P + p];
            if (relu) v = fmaxf(v, 0.f);
            out[o * P + p] = v;
        }
    }
}

// ---------------------------------------------------------------------------
// Big GEMM (64P x 128O tile, 8x4 microtile, float4 LDS) for P >= 4096.
// ---------------------------------------------------------------------------
__global__ __launch_bounds__(256) void gemm_big_k(
    const float* __restrict__ W, const float* __restrict__ bias,
    const float* __restrict__ X, const float* __restrict__ X2,
    const float* __restrict__ addp, float* __restrict__ out,
    int I, int P, int relu)
{
    __shared__ float Ws[16][132];
    __shared__ float Xs[16][64];
    int tid = threadIdx.x;
    int tx = tid & 15, ty = tid >> 4;
    int pc = blockIdx.x * 64;
    int oc = blockIdx.y * 128;
    float acc[8][4] = {};
    for (int kc = 0; kc < I; kc += 16) {
#pragma unroll
        for (int r = 0; r < 8; r++) {
            int e = tid + r * 256;
            int ol = e >> 4, kl = e & 15;
            Ws[kl][ol] = W[(oc + ol) * I + kc + kl];
        }
#pragma unroll
        for (int r = 0; r < 4; r++) {
            int e = tid + r * 256;
            int kl = e >> 6, pl = e & 63;
            int gi = kc + kl;
            const float* src = (X2 != nullptr && gi >= 256) ? (X2 + (gi - 256) * P)
                                                            : (X + gi * P);
            Xs[kl][pl] = src[pc + pl];
        }
        __syncthreads();
#pragma unroll
        for (int kk = 0; kk < 16; kk++) {
            float4 a0 = *(const float4*)&Ws[kk][ty * 8];
            float4 a1 = *(const float4*)&Ws[kk][ty * 8 + 4];
            float4 bb = *(const float4*)&Xs[kk][tx * 4];
            float a[8] = {a0.x, a0.y, a0.z, a0.w, a1.x, a1.y, a1.z, a1.w};
            float b[4] = {bb.x, bb.y, bb.z, bb.w};
#pragma unroll
            for (int i = 0; i < 8; i++)
#pragma unroll
                for (int j = 0; j < 4; j++) acc[i][j] += a[i] * b[j];
        }
        __syncthreads();
    }
#pragma unroll
    for (int i = 0; i < 8; i++) {
        int o = oc + ty * 8 + i;
        float bv = bias ? bias[o] : 0.f;
#pragma unroll
        for (int j = 0; j < 4; j++) {
            int p = pc + tx * 4 + j;
            float v = acc[i][j] + bv;
            if (addp) v += addp[o * P + p];
            if (relu) v = fmaxf(v, 0.f);
            out[o * P + p] = v;
        }
    }
}

// ---------------------------------------------------------------------------
// Multi-head attention, HD=64, H=4, channel = hd*4+h. One thread per query.
// ---------------------------------------------------------------------------
__global__ __launch_bounds__(64) void attn_k(
    const float* __restrict__ qF, const float* __restrict__ kF,
    const float* __restrict__ vF, float* __restrict__ msg,
    int Pq, int Pk, int nq, int nk)
{
    __shared__ float ks[64][64];
    __shared__ float vs[64][64];
    int tid = threadIdx.x;
    int h = blockIdx.y;
    int bz = blockIdx.z;
    int ql = blockIdx.x * 64 + tid;
    bool active = ql < nq;
    int qpos = bz * nq + (active ? ql : 0);
    float qr[64];
#pragma unroll
    for (int hd = 0; hd < 64; hd++)
        qr[hd] = active ? qF[(hd * 4 + h) * Pq + qpos] : 0.f;
    float mx = -1e30f, sm = 0.f;
    float acc[64];
#pragma unroll
    for (int hd = 0; hd < 64; hd++) acc[hd] = 0.f;

    for (int kt = 0; kt < nk; kt += 64) {
        int m = kt + tid;
        bool kok = m < nk;
        int kpos = bz * nk + (kok ? m : 0);
#pragma unroll
        for (int hd = 0; hd < 64; hd++) {
            ks[hd][tid] = kok ? kF[(hd * 4 + h) * Pk + kpos] : 0.f;
            vs[hd][tid] = kok ? vF[(hd * 4 + h) * Pk + kpos] : 0.f;
        }
        __syncthreads();
        if (active) {
            int mmax = min(64, nk - kt);
            for (int ml = 0; ml < mmax; ml++) {
                float s = 0.f;
#pragma unroll
                for (int hd = 0; hd < 64; hd++) s += qr[hd] * ks[hd][ml];
                s *= 0.125f;
                float p;
                if (s > mx) {
                    float c = __expf(mx - s);
                    sm *= c;
#pragma unroll
                    for (int hd = 0; hd < 64; hd++) acc[hd] *= c;
                    mx = s;
                    p = 1.f;
                } else {
                    p = __expf(s - mx);
                }
                sm += p;
#pragma unroll
                for (int hd = 0; hd < 64; hd++) acc[hd] += p * vs[hd][ml];
            }
        }
        __syncthreads();
    }
    if (active) {
        float inv = 1.f / sm;
#pragma unroll
        for (int hd = 0; hd < 64; hd++)
            msg[(hd * 4 + h) * Pq + qpos] = acc[hd] * inv;
    }
}

// ---------------------------------------------------------------------------
// Gathers / positional encodings / pooling
// ---------------------------------------------------------------------------
__global__ void gather_trk(const float* __restrict__ tracks, float* __restrict__ o)
{
    int idx = blockIdx.x * 256 + threadIdx.x;
    if (idx >= 256 * P_TRK) return;
    int c = idx >> 14, p = idx & 16383;
    int bi = p >> 4, t = p & 15;
    o[idx] = tracks[bi * 4112 + (c + 1) * 16 + t];
}
__global__ void gather_det(const float* __restrict__ det, float* __restrict__ o)
{
    int idx = blockIdx.x * 256 + threadIdx.x;
    if (idx >= 256 * P_DET) return;
    int c = idx >> 12, p = idx & 4095;
    int b = p >> 10, m = p & 1023;
    o[idx] = det[b * 263168 + (c + 1) * 1024 + m];
}
__global__ void pe_trk_k(const float* __restrict__ tracks, float* __restrict__ pe)
{
    int idx = blockIdx.x * 256 + threadIdx.x;
    if (idx >= 256 * P_TRK) return;
    int c = idx >> 14, p = idx & 16383;
    int bi = p >> 4, t = p & 15;
    float pos = tracks[bi * 4112 + t];
    float dv = expf((float)(c & ~1) * (-9.210340371976184f / 256.f));
    float ang = pos * dv;
    pe[idx] = (c & 1) ? cosf(ang) : sinf(ang);
}
__global__ void pe_det_k(const float* __restrict__ det, float* __restrict__ pe)
{
    int idx = blockIdx.x * 256 + threadIdx.x;
    if (idx >= 256 * P_DET) return;
    int c = idx >> 12, p = idx & 4095;
    int b = p >> 10, m = p & 1023;
    float pos = det[b * 263168 + m];
    float dv = expf((float)(c & ~1) * (-9.210340371976184f / 256.f));
    float ang = pos * dv;
    pe[idx] = (c & 1) ? cosf(ang) : sinf(ang);
}
__global__ void pool_k(const float* __restrict__ x, float* __restrict__ tr)
{
    int idx = blockIdx.x * 256 + threadIdx.x;
    if (idx >= 256 * P_TR) return;
    int c = idx >> 10, bi = idx & 1023;
    const float* p = x + c * P_TRK + bi * 16;
    float s = 0.f;
#pragma unroll
    for (int t = 0; t < 16; t++) s += p[t];
    tr[idx] = s * 0.0625f;
}

// ---------------------------------------------------------------------------
// scores -> Z0 (top-left block)
// ---------------------------------------------------------------------------
__global__ __launch_bounds__(256) void scores_k(
    const float* __restrict__ m0, const float* __restrict__ m1, float* __restrict__ Z0)
{
    __shared__ float As[16][64];
    __shared__ float Bs[16][64];
    int tid = threadIdx.x, tx = tid & 15, ty = tid >> 4;
    int b = blockIdx.z;
    int nc = blockIdx.y * 64, mc = blockIdx.x * 64;
    float acc[4][4] = {};
    for (int kc = 0; kc < 256; kc += 16) {
#pragma unroll
        for (int r = 0; r < 4; r++) {
            int e = tid + r * 256;
            int kl = e >> 6, nl = e & 63;
            As[kl][nl] = m0[(kc + kl) * P_TR + b * 256 + nc + nl];
        }
#pragma unroll
        for (int r = 0; r < 4; r++) {
            int e = tid + r * 256;
            int kl = e >> 6, ml = e & 63;
            Bs[kl][ml] = m1[(kc + kl) * P_DET + b * 1024 + mc + ml];
        }
        __syncthreads();
#pragma unroll
        for (int kk = 0; kk < 16; kk++) {
            float a[4], bb[4];
#pragma unroll
            for (int i = 0; i < 4; i++) a[i] = As[kk][ty * 4 + i];
#pragma unroll
            for (int j = 0; j < 4; j++) bb[j] = Bs[kk][tx * 4 + j];
#pragma unroll
            for (int i = 0; i < 4; i++)
#pragma unroll
                for (int j = 0; j < 4; j++) acc[i][j] += a[i] * bb[j];
        }
        __syncthreads();
    }
#pragma unroll
    for (int i = 0; i < 4; i++) {
        int n = nc + ty * 4 + i;
#pragma unroll
        for (int j = 0; j < 4; j++) {
            int m = mc + tx * 4 + j;
            Z0[b * ZROW + n * 1025 + m] = acc[i][j] * 0.0625f;
        }
    }
}

__global__ void fill_bins(float* __restrict__ Z0, const float* __restrict__ alpha_p)
{
    float a = *alpha_p;
    int idx = blockIdx.x * 256 + threadIdx.x;
    if (idx < 1024) {
        int b = idx >> 8, i = idx & 255;
        Z0[b * ZROW + i * 1025 + 1024] = a;
    }
    int idx2 = idx - 1024;
    if (idx2 >= 0 && idx2 < 4100) {
        int b = idx2 / 1025, j = idx2 % 1025;
        Z0[b * ZROW + 256 * 1025 + j] = a;
    }
}

__global__ void zero_k(float* p, int n)
{
    int i = blockIdx.x * 256 + threadIdx.x;
    if (i < n) p[i] = 0.f;
}

// ---------------------------------------------------------------------------
// Fused Sinkhorn: one persistent kernel, software grid barrier (148 blocks).
// ---------------------------------------------------------------------------
__device__ __forceinline__ void lse_merge(float& m, float& s, float om, float os)
{
    float M = fmaxf(m, om);
    s = s * __expf(m - M) + os * __expf(om - M);
    m = M;
}

__device__ __forceinline__ void grid_bar(unsigned* cnt, unsigned target)
{
    __syncthreads();
    if (threadIdx.x == 0) {
        __threadfence();
        atomicAdd(cnt, 1u);
        volatile unsigned* vc = cnt;
        while (*vc < target * (unsigned)NBLK_SINK) {}
        __threadfence();
    }
    __syncthreads();
}

__global__ __launch_bounds__(256) void sink_fused_k(
    const float* __restrict__ Z0, float* __restrict__ u, float* __restrict__ v,
    unsigned* __restrict__ cnt)
{
    __shared__ float smm[8], sss[8];
    __shared__ float smm2[8][33], sss2[8][33];
    int tid = threadIdx.x;
    int w = tid >> 5, l = tid & 31;
    unsigned phase = 0;

    for (int it = 0; it < 100; it++) {
        // ---- u update (reads v) ----
        for (int row = blockIdx.x; row < 1028; row += NBLK_SINK) {
            int b = row / 257, i = row % 257;
            const float* zr = Z0 + b * ZROW + i * 1025;
            const float* vb = v + b * 1025;
            float m = -1e30f, s = 0.f;
            for (int j = tid; j < 1025; j += 256) {
                float z = zr[j] + vb[j];
                if (z > m) { s = s * __expf(m - z) + 1.f; m = z; }
                else s += __expf(z - m);
            }
            for (int off = 16; off; off >>= 1) {
                float om = __shfl_down_sync(0xffffffffu, m, off);
                float os = __shfl_down_sync(0xffffffffu, s, off);
                lse_merge(m, s, om, os);
            }
            if (l == 0) { smm[w] = m; sss[w] = s; }
            __syncthreads();
            if (tid == 0) {
                m = smm[0]; s = sss[0];
                for (int k = 1; k < 8; k++) lse_merge(m, s, smm[k], sss[k]);
                float logmu = (i < 256) ? NORM_C : (NORM_C + LOG1024);
                u[row] = logmu - (m + __logf(s));
            }
            __syncthreads();
        }
        phase++; grid_bar(cnt, phase);

        // ---- v update (reads u) ----
        for (int task = blockIdx.x; task < 132; task += NBLK_SINK) {
            int b = task / 33, jt = task % 33;
            int j = jt * 32 + l;
            float m = -1e30f, s = 0.f;
            if (j < 1025) {
                const float* zb = Z0 + b * ZROW;
                const float* ub = u + b * 257;
                for (int i = w; i < 257; i += 8) {
                    float z = zb[i * 1025 + j] + ub[i];
                    if (z > m) { s = s * __expf(m - z) + 1.f; m = z; }
                    else s += __expf(z - m);
                }
            }
            smm2[w][l] = m; sss2[w][l] = s;
            __syncthreads();
            if (w == 0 && j < 1025) {
                m = smm2[0][l]; s = sss2[0][l];
                for (int k = 1; k < 8; k++) lse_merge(m, s, smm2[k][l], sss2[k][l]);
                float lognu = (j < 1024) ? NORM_C : (NORM_C + LOG256);
                v[b * 1025 + j] = lognu - (m + __logf(s));
            }
            __syncthreads();
        }
        phase++; grid_bar(cnt, phase);
    }
}

__global__ void sink_out(const float* __restrict__ Z0, const float* __restrict__ u,
                         const float* __restrict__ v, float* __restrict__ out)
{
    int idx = blockIdx.x * 256 + threadIdx.x;
    if (idx >= 4 * ZROW) return;
    int b = idx / ZROW;
    int r = idx - b * ZROW;
    int i = r / 1025, j = r - i * 1025;
    out[idx] = Z0[idx] + u[b * 257 + i] + v[b * 1025 + j] - NORM_C;
}

// ---------------------------------------------------------------------------
// Host orchestration
// ---------------------------------------------------------------------------
static void gemm(const float* W, const float* bias, const float* X, const float* X2,
                 const float* addp, float* out, int O, int I, int P, int relu)
{
    if (P >= 4096 && (O % 128) == 0) {
        dim3 g(P / 64, O / 128);
        gemm_big_k<<<g, 256>>>(W, bias, X, X2, addp, out, I, P, relu);
    } else {
        dim3 g(P / 64, O / 64);
        gemm_k<<<g, 256>>>(W, bias, X, X2, addp, out, I, P, relu);
    }
}

extern "C" void kernel_launch(void* const* d_in, const int* in_sizes, int n_in,
                              void* d_out, int out_size)
{
    const float* detections = (const float*)d_in[0];
    const float* tracks     = (const float*)d_in[1];
    const float* enc_w1 = (const float*)d_in[2];
    const float* enc_b1 = (const float*)d_in[3];
    const float* enc_w2 = (const float*)d_in[4];
    const float* enc_b2 = (const float*)d_in[5];
    const float* fus_pw  = (const float*)d_in[6];
    const float* fus_pb  = (const float*)d_in[7];
    const float* fus_mw  = (const float*)d_in[8];
    const float* fus_mb  = (const float*)d_in[9];
    const float* fus_m1w = (const float*)d_in[10];
    const float* fus_m1b = (const float*)d_in[11];
    const float* fus_m2w = (const float*)d_in[12];
    const float* fus_m2b = (const float*)d_in[13];
    const float* gnn_pw  = (const float*)d_in[14];
    const float* gnn_pb  = (const float*)d_in[15];
    const float* gnn_mw  = (const float*)d_in[16];
    const float* gnn_mb  = (const float*)d_in[17];
    const float* gnn_m1w = (const float*)d_in[18];
    const float* gnn_m1b = (const float*)d_in[19];
    const float* gnn_m2w = (const float*)d_in[20];
    const float* gnn_m2b = (const float*)d_in[21];
    const float* final_w = (const float*)d_in[22];
    const float* final_b = (const float*)d_in[23];
    const float* bin_score = (const float*)d_in[24];
    float* out = (float*)d_out;

    float* pool = nullptr;
    cudaGetSymbolAddress((void**)&pool, g_pool);
    size_t off = 0;
    auto carve = [&](size_t n) { float* p = pool + off; off += n; return p; };
    float* TRKIN = carve(4194304);
    float* DETIN = carve(1048576);
    float* TRKPE = carve(4194304);
    float* DETPE = carve(1048576);
    float* TMP1  = carve(8388608);
    float* QKV   = carve(12582912);
    float* MSG   = carve(4194304);
    float* MSG2  = carve(4194304);
    float* XA    = carve(4194304);
    float* XB    = carve(4194304);
    float* DETA  = carve(1048576);
    float* DETB  = carve(1048576);
    float* TRA   = carve(262144);
    float* TRB   = carve(262144);
    float* M0b   = carve(262144);
    float* M1b   = carve(1048576);
    float* Z0    = carve(1053700);
    float* U     = carve(1028);
    float* V     = carve(4100);
    float* CNT   = carve(4);

    // ---- gathers + positional encodings ----
    gather_trk<<<16384, 256>>>(tracks, TRKIN);
    gather_det<<<4096, 256>>>(detections, DETIN);
    pe_trk_k<<<16384, 256>>>(tracks, TRKPE);
    pe_det_k<<<4096, 256>>>(detections, DETPE);

    // ---- encoders (pe add folded into second GEMM) ----
    gemm(enc_w1, enc_b1, TRKIN, nullptr, nullptr, TMP1, 256, 256, P_TRK, 1);
    gemm(enc_w2, enc_b2, TMP1, nullptr, TRKPE, XA, 256, 256, P_TRK, 0);
    gemm(enc_w1, enc_b1, DETIN, nullptr, nullptr, TMP1, 256, 256, P_DET, 1);
    gemm(enc_w2, enc_b2, TMP1, nullptr, DETPE, DETA, 256, 256, P_DET, 0);

    // ---- fuser: 4 self-attention layers over T=16 ----
    float* x = XA; float* xo = XB;
    for (int l = 0; l < 4; l++) {
        const float* pw = fus_pw + l * 196608;
        const float* pb = fus_pb + l * 768;
        gemm(pw, pb, x, nullptr, nullptr, QKV, 768, 256, P_TRK, 0);  // fused QKV
        attn_k<<<dim3(1, 4, 1024), 64>>>(QKV, QKV + 256 * P_TRK, QKV + 512 * P_TRK,
                                         MSG, P_TRK, P_TRK, 16, 16);
        gemm(fus_mw + l * 65536, fus_mb + l * 256, MSG, nullptr, nullptr, MSG2,
             256, 256, P_TRK, 0);
        gemm(fus_m1w + l * 262144, fus_m1b + l * 512, x, MSG2, nullptr, TMP1,
             512, 512, P_TRK, 1);
        gemm(fus_m2w + l * 131072, fus_m2b + l * 256, TMP1, nullptr, x, xo,
             256, 512, P_TRK, 0);
        float* t = x; x = xo; xo = t;
    }
    pool_k<<<1024, 256>>>(x, TRA);

    // ---- GNN: 12 alternating self/cross layers ----
    float* tr = TRA; float* tro = TRB;
    float* de = DETA; float* deo = DETB;
    for (int l = 0; l < 12; l++) {
        const float* pw  = gnn_pw + l * 196608;
        const float* pb  = gnn_pb + l * 768;
        const float* mw  = gnn_mw + l * 65536;
        const float* mb  = gnn_mb + l * 256;
        const float* m1w = gnn_m1w + l * 262144;
        const float* m1b = gnn_m1b + l * 512;
        const float* m2w = gnn_m2w + l * 131072;
        const float* m2b = gnn_m2b + l * 256;
        int cross = l & 1;

        // d0: queries = tr
        if (!cross) {
            gemm(pw, pb, tr, nullptr, nullptr, QKV, 768, 256, P_TR, 0);
            attn_k<<<dim3(4, 4, 4), 64>>>(QKV, QKV + 256 * P_TR, QKV + 512 * P_TR,
                                          MSG, P_TR, P_TR, 256, 256);
        } else {
            gemm(pw, pb, tr, nullptr, nullptr, QKV, 256, 256, P_TR, 0);
            float* kvb = QKV + 256 * P_TR;
            gemm(pw + 65536, pb + 256, de, nullptr, nullptr, kvb, 512, 256, P_DET, 0);
            attn_k<<<dim3(4, 4, 4), 64>>>(QKV, kvb, kvb + 256 * P_DET,
                                          MSG, P_TR, P_DET, 256, 1024);
        }
        gemm(mw, mb, MSG, nullptr, nullptr, MSG2, 256, 256, P_TR, 0);
        gemm(m1w, m1b, tr, MSG2, nullptr, TMP1, 512, 512, P_TR, 1);
        gemm(m2w, m2b, TMP1, nullptr, tr, tro, 256, 512, P_TR, 0);

        // d1: queries = det (uses OLD tr)
        if (!cross) {
            gemm(pw, pb, de, nullptr, nullptr, QKV, 768, 256, P_DET, 0);
            attn_k<<<dim3(16, 4, 4), 64>>>(QKV, QKV + 256 * P_DET, QKV + 512 * P_DET,
                                           MSG, P_DET, P_DET, 1024, 1024);
        } else {
            gemm(pw, pb, de, nullptr, nullptr, QKV, 256, 256, P_DET, 0);
            float* kvb = QKV + 256 * P_DET;
            gemm(pw + 65536, pb + 256, tr, nullptr, nullptr, kvb, 512, 256, P_TR, 0);
            attn_k<<<dim3(16, 4, 4), 64>>>(QKV, kvb, kvb + 256 * P_TR,
                                           MSG, P_DET, P_TR, 1024, 256);
        }
        gemm(mw, mb, MSG, nullptr, nullptr, MSG2, 256, 256, P_DET, 0);
        gemm(m1w, m1b, de, MSG2, nullptr, TMP1, 512, 512, P_DET, 1);
        gemm(m2w, m2b, TMP1, nullptr, de, deo, 256, 512, P_DET, 0);

        float* t = tr; tr = tro; tro = t;
        t = de; de = deo; deo = t;
    }

    // ---- final projections + scores + Sinkhorn ----
    gemm(final_w, final_b, tr, nullptr, nullptr, M0b, 256, 256, P_TR, 0);
    gemm(final_w, final_b, de, nullptr, nullptr, M1b, 256, 256, P_DET, 0);
    scores_k<<<dim3(16, 4, 4), 256>>>(M0b, M1b, Z0);
    fill_bins<<<21, 256>>>(Z0, bin_score);
    zero_k<<<21, 256>>>(U, 5129);  // U (1028) + V (4100) + CNT (1), contiguous

    sink_fused_k<<<NBLK_SINK, 256>>>(Z0, U, V, (unsigned*)CNT);
    sink_out<<<(4 * ZROW + 255) / 256, 256>>>(Z0, U, V, out);
    (void)in_sizes; (void)n_in; (void)out_size;
}

// round 3
// speedup vs baseline: 1.0633x; 1.0633x over previous
#include <cuda_runtime.h>
#include <math.h>

// B=4, N_TR=256, M_DET=1024, T=16, D=256, H=4, HD=64, N_FUSER=4, N_GNN=12, ITERS=100
#define P_TRK 16384
#define P_DET 4096
#define P_TR  1024
#define ZROW  263425  // 257*1025
#define NORM_C  (-7.1546153569136625f)  /* -ln(1280) */
#define LOG1024 6.931471805599453f
#define LOG256  5.545177444479562f
#define NBLK_SINK 148

__device__ float g_pool[54000000];

// ---------------------------------------------------------------------------
// Double-buffered GEMM: 128(O) x 64(P) tile, K-step 16, 8x4 microtile.
// out[o,p] = act( sum_i W[o,i]*X[i,p] + bias[o] + add[o,p] ); X2: rows i>=256.
// Requires O%128==0, I%16==0, P%64==0.
// ---------------------------------------------------------------------------
__global__ __launch_bounds__(256) void gemm_db_k(
    const float* __restrict__ W, const float* __restrict__ bias,
    const float* __restrict__ X, const float* __restrict__ X2,
    const float* __restrict__ addp, float* __restrict__ out,
    int I, int P, int relu)
{
    __shared__ float Ws[2][16][132];
    __shared__ float Xs[2][16][68];
    int tid = threadIdx.x;
    int tx = tid & 15, ty = tid >> 4;
    int pc = blockIdx.x * 64;
    int oc = blockIdx.y * 128;

    // loader indices
    int wol = tid >> 4, wkl = tid & 15;      // +r*16 on ol, r=0..7
    int xkl = tid >> 6, xpl = tid & 63;      // +r*4 on kl, r=0..3

    float wreg[8], xreg[4];

    // prefetch tile 0
#pragma unroll
    for (int r = 0; r < 8; r++)
        wreg[r] = W[(oc + wol + r * 16) * I + wkl];
#pragma unroll
    for (int r = 0; r < 4; r++) {
        int gi = xkl + r * 4;
        const float* src = (X2 != nullptr && gi >= 256) ? (X2 + (gi - 256) * P)
                                                        : (X + gi * P);
        xreg[r] = src[pc + xpl];
    }
#pragma unroll
    for (int r = 0; r < 8; r++) Ws[0][wkl][wol + r * 16] = wreg[r];
#pragma unroll
    for (int r = 0; r < 4; r++) Xs[0][xkl + r * 4][xpl] = xreg[r];
    __syncthreads();

    float acc[8][4] = {};
    int buf = 0;
    for (int kc = 0; kc < I; kc += 16) {
        int more = (kc + 16 < I);
        if (more) {
            int kn = kc + 16;
#pragma unroll
            for (int r = 0; r < 8; r++)
                wreg[r] = W[(oc + wol + r * 16) * I + kn + wkl];
#pragma unroll
            for (int r = 0; r < 4; r++) {
                int gi = kn + xkl + r * 4;
                const float* src = (X2 != nullptr && gi >= 256) ? (X2 + (gi - 256) * P)
                                                                : (X + gi * P);
                xreg[r] = src[pc + xpl];
            }
        }
        // compute current tile (overlaps the LDGs above)
#pragma unroll
        for (int kk = 0; kk < 16; kk++) {
            float4 a0 = *(const float4*)&Ws[buf][kk][ty * 8];
            float4 a1 = *(const float4*)&Ws[buf][kk][ty * 8 + 4];
            float4 bb = *(const float4*)&Xs[buf][kk][tx * 4];
            float a[8] = {a0.x, a0.y, a0.z, a0.w, a1.x, a1.y, a1.z, a1.w};
            float b[4] = {bb.x, bb.y, bb.z, bb.w};
#pragma unroll
            for (int i = 0; i < 8; i++)
#pragma unroll
                for (int j = 0; j < 4; j++) acc[i][j] += a[i] * b[j];
        }
        if (more) {
#pragma unroll
            for (int r = 0; r < 8; r++) Ws[buf ^ 1][wkl][wol + r * 16] = wreg[r];
#pragma unroll
            for (int r = 0; r < 4; r++) Xs[buf ^ 1][xkl + r * 4][xpl] = xreg[r];
        }
        __syncthreads();
        buf ^= 1;
    }
#pragma unroll
    for (int i = 0; i < 8; i++) {
        int o = oc + ty * 8 + i;
        float bv = bias ? bias[o] : 0.f;
#pragma unroll
        for (int j = 0; j < 4; j++) {
            int p = pc + tx * 4 + j;
            float v = acc[i][j] + bv;
            if (addp) v += addp[o * P + p];
            if (relu) v = fmaxf(v, 0.f);
            out[o * P + p] = v;
        }
    }
}

// ---------------------------------------------------------------------------
// Multi-head attention, HD=64, H=4, channel = hd*4+h. One thread per query.
// ---------------------------------------------------------------------------
__global__ __launch_bounds__(64) void attn_k(
    const float* __restrict__ qF, const float* __restrict__ kF,
    const float* __restrict__ vF, float* __restrict__ msg,
    int Pq, int Pk, int nq, int nk)
{
    __shared__ float ks[64][64];
    __shared__ float vs[64][64];
    int tid = threadIdx.x;
    int h = blockIdx.y;
    int bz = blockIdx.z;
    int ql = blockIdx.x * 64 + tid;
    bool active = ql < nq;
    int qpos = bz * nq + (active ? ql : 0);
    float qr[64];
#pragma unroll
    for (int hd = 0; hd < 64; hd++)
        qr[hd] = active ? qF[(hd * 4 + h) * Pq + qpos] : 0.f;
    float mx = -1e30f, sm = 0.f;
    float acc[64];
#pragma unroll
    for (int hd = 0; hd < 64; hd++) acc[hd] = 0.f;

    for (int kt = 0; kt < nk; kt += 64) {
        int m = kt + tid;
        bool kok = m < nk;
        int kpos = bz * nk + (kok ? m : 0);
#pragma unroll
        for (int hd = 0; hd < 64; hd++) {
            ks[hd][tid] = kok ? kF[(hd * 4 + h) * Pk + kpos] : 0.f;
            vs[hd][tid] = kok ? vF[(hd * 4 + h) * Pk + kpos] : 0.f;
        }
        __syncthreads();
        if (active) {
            int mmax = min(64, nk - kt);
            for (int ml = 0; ml < mmax; ml++) {
                float s = 0.f;
#pragma unroll
                for (int hd = 0; hd < 64; hd++) s += qr[hd] * ks[hd][ml];
                s *= 0.125f;
                float p;
                if (s > mx) {
                    float c = __expf(mx - s);
                    sm *= c;
#pragma unroll
                    for (int hd = 0; hd < 64; hd++) acc[hd] *= c;
                    mx = s;
                    p = 1.f;
                } else {
                    p = __expf(s - mx);
                }
                sm += p;
#pragma unroll
                for (int hd = 0; hd < 64; hd++) acc[hd] += p * vs[hd][ml];
            }
        }
        __syncthreads();
    }
    if (active) {
        float inv = 1.f / sm;
#pragma unroll
        for (int hd = 0; hd < 64; hd++)
            msg[(hd * 4 + h) * Pq + qpos] = acc[hd] * inv;
    }
}

// ---------------------------------------------------------------------------
// Gathers / positional encodings / pooling
// ---------------------------------------------------------------------------
__global__ void gather_trk(const float* __restrict__ tracks, float* __restrict__ o)
{
    int idx = blockIdx.x * 256 + threadIdx.x;
    if (idx >= 256 * P_TRK) return;
    int c = idx >> 14, p = idx & 16383;
    int bi = p >> 4, t = p & 15;
    o[idx] = tracks[bi * 4112 + (c + 1) * 16 + t];
}
__global__ void gather_det(const float* __restrict__ det, float* __restrict__ o)
{
    int idx = blockIdx.x * 256 + threadIdx.x;
    if (idx >= 256 * P_DET) return;
    int c = idx >> 12, p = idx & 4095;
    int b = p >> 10, m = p & 1023;
    o[idx] = det[b * 263168 + (c + 1) * 1024 + m];
}
__global__ void pe_trk_k(const float* __restrict__ tracks, float* __restrict__ pe)
{
    int idx = blockIdx.x * 256 + threadIdx.x;
    if (idx >= 256 * P_TRK) return;
    int c = idx >> 14, p = idx & 16383;
    int bi = p >> 4, t = p & 15;
    float pos = tracks[bi * 4112 + t];
    float dv = expf((float)(c & ~1) * (-9.210340371976184f / 256.f));
    float ang = pos * dv;
    pe[idx] = (c & 1) ? cosf(ang) : sinf(ang);
}
__global__ void pe_det_k(const float* __restrict__ det, float* __restrict__ pe)
{
    int idx = blockIdx.x * 256 + threadIdx.x;
    if (idx >= 256 * P_DET) return;
    int c = idx >> 12, p = idx & 4095;
    int b = p >> 10, m = p & 1023;
    float pos = det[b * 263168 + m];
    float dv = expf((float)(c & ~1) * (-9.210340371976184f / 256.f));
    float ang = pos * dv;
    pe[idx] = (c & 1) ? cosf(ang) : sinf(ang);
}
__global__ void pool_k(const float* __restrict__ x, float* __restrict__ tr)
{
    int idx = blockIdx.x * 256 + threadIdx.x;
    if (idx >= 256 * P_TR) return;
    int c = idx >> 10, bi = idx & 1023;
    const float* p = x + c * P_TRK + bi * 16;
    float s = 0.f;
#pragma unroll
    for (int t = 0; t < 16; t++) s += p[t];
    tr[idx] = s * 0.0625f;
}

// ---------------------------------------------------------------------------
// scores -> Z0 (top-left block)
// ---------------------------------------------------------------------------
__global__ __launch_bounds__(256) void scores_k(
    const float* __restrict__ m0, const float* __restrict__ m1, float* __restrict__ Z0)
{
    __shared__ float As[16][64];
    __shared__ float Bs[16][64];
    int tid = threadIdx.x, tx = tid & 15, ty = tid >> 4;
    int b = blockIdx.z;
    int nc = blockIdx.y * 64, mc = blockIdx.x * 64;
    float acc[4][4] = {};
    for (int kc = 0; kc < 256; kc += 16) {
#pragma unroll
        for (int r = 0; r < 4; r++) {
            int e = tid + r * 256;
            int kl = e >> 6, nl = e & 63;
            As[kl][nl] = m0[(kc + kl) * P_TR + b * 256 + nc + nl];
        }
#pragma unroll
        for (int r = 0; r < 4; r++) {
            int e = tid + r * 256;
            int kl = e >> 6, ml = e & 63;
            Bs[kl][ml] = m1[(kc + kl) * P_DET + b * 1024 + mc + ml];
        }
        __syncthreads();
#pragma unroll
        for (int kk = 0; kk < 16; kk++) {
            float a[4], bb[4];
#pragma unroll
            for (int i = 0; i < 4; i++) a[i] = As[kk][ty * 4 + i];
#pragma unroll
            for (int j = 0; j < 4; j++) bb[j] = Bs[kk][tx * 4 + j];
#pragma unroll
            for (int i = 0; i < 4; i++)
#pragma unroll
                for (int j = 0; j < 4; j++) acc[i][j] += a[i] * bb[j];
        }
        __syncthreads();
    }
#pragma unroll
    for (int i = 0; i < 4; i++) {
        int n = nc + ty * 4 + i;
#pragma unroll
        for (int j = 0; j < 4; j++) {
            int m = mc + tx * 4 + j;
            Z0[b * ZROW + n * 1025 + m] = acc[i][j] * 0.0625f;
        }
    }
}

__global__ void fill_bins(float* __restrict__ Z0, const float* __restrict__ alpha_p)
{
    float a = *alpha_p;
    int idx = blockIdx.x * 256 + threadIdx.x;
    if (idx < 1024) {
        int b = idx >> 8, i = idx & 255;
        Z0[b * ZROW + i * 1025 + 1024] = a;
    }
    int idx2 = idx - 1024;
    if (idx2 >= 0 && idx2 < 4100) {
        int b = idx2 / 1025, j = idx2 % 1025;
        Z0[b * ZROW + 256 * 1025 + j] = a;
    }
}

__global__ void zero_k(float* p, int n)
{
    int i = blockIdx.x * 256 + threadIdx.x;
    if (i < n) p[i] = 0.f;
}

// ---------------------------------------------------------------------------
// Fused Sinkhorn: persistent kernel, software grid barrier (148 blocks).
// ---------------------------------------------------------------------------
__device__ __forceinline__ void lse_merge(float& m, float& s, float om, float os)
{
    float M = fmaxf(m, om);
    s = s * __expf(m - M) + os * __expf(om - M);
    m = M;
}

__device__ __forceinline__ void grid_bar(unsigned* cnt, unsigned target)
{
    __syncthreads();
    if (threadIdx.x == 0) {
        __threadfence();
        atomicAdd(cnt, 1u);
        volatile unsigned* vc = cnt;
        while (*vc < target * (unsigned)NBLK_SINK) {}
        __threadfence();
    }
    __syncthreads();
}

__global__ __launch_bounds__(256) void sink_fused_k(
    const float* __restrict__ Z0, float* __restrict__ u, float* __restrict__ v,
    unsigned* __restrict__ cnt)
{
    __shared__ float smm[8], sss[8];
    __shared__ float smm2[8][33], sss2[8][33];
    int tid = threadIdx.x;
    int w = tid >> 5, l = tid & 31;
    unsigned phase = 0;

    for (int it = 0; it < 100; it++) {
        for (int row = blockIdx.x; row < 1028; row += NBLK_SINK) {
            int b = row / 257, i = row % 257;
            const float* zr = Z0 + b * ZROW + i * 1025;
            const float* vb = v + b * 1025;
            float m = -1e30f, s = 0.f;
            for (int j = tid; j < 1025; j += 256) {
                float z = zr[j] + vb[j];
                if (z > m) { s = s * __expf(m - z) + 1.f; m = z; }
                else s += __expf(z - m);
            }
            for (int off = 16; off; off >>= 1) {
                float om = __shfl_down_sync(0xffffffffu, m, off);
                float os = __shfl_down_sync(0xffffffffu, s, off);
                lse_merge(m, s, om, os);
            }
            if (l == 0) { smm[w] = m; sss[w] = s; }
            __syncthreads();
            if (tid == 0) {
                m = smm[0]; s = sss[0];
                for (int k = 1; k < 8; k++) lse_merge(m, s, smm[k], sss[k]);
                float logmu = (i < 256) ? NORM_C : (NORM_C + LOG1024);
                u[row] = logmu - (m + __logf(s));
            }
            __syncthreads();
        }
        phase++; grid_bar(cnt, phase);

        for (int task = blockIdx.x; task < 132; task += NBLK_SINK) {
            int b = task / 33, jt = task % 33;
            int j = jt * 32 + l;
            float m = -1e30f, s = 0.f;
            if (j < 1025) {
                const float* zb = Z0 + b * ZROW;
                const float* ub = u + b * 257;
                for (int i = w; i < 257; i += 8) {
                    float z = zb[i * 1025 + j] + ub[i];
                    if (z > m) { s = s * __expf(m - z) + 1.f; m = z; }
                    else s += __expf(z - m);
                }
            }
            smm2[w][l] = m; sss2[w][l] = s;
            __syncthreads();
            if (w == 0 && j < 1025) {
                m = smm2[0][l]; s = sss2[0][l];
                for (int k = 1; k < 8; k++) lse_merge(m, s, smm2[k][l], sss2[k][l]);
                float lognu = (j < 1024) ? NORM_C : (NORM_C + LOG256);
                v[b * 1025 + j] = lognu - (m + __logf(s));
            }
            __syncthreads();
        }
        phase++; grid_bar(cnt, phase);
    }
}

__global__ void sink_out(const float* __restrict__ Z0, const float* __restrict__ u,
                         const float* __restrict__ v, float* __restrict__ out)
{
    int idx = blockIdx.x * 256 + threadIdx.x;
    if (idx >= 4 * ZROW) return;
    int b = idx / ZROW;
    int r = idx - b * ZROW;
    int i = r / 1025, j = r - i * 1025;
    out[idx] = Z0[idx] + u[b * 257 + i] + v[b * 1025 + j] - NORM_C;
}

// ---------------------------------------------------------------------------
// Host orchestration
// ---------------------------------------------------------------------------
static void gemm(const float* W, const float* bias, const float* X, const float* X2,
                 const float* addp, float* out, int O, int I, int P, int relu)
{
    dim3 g(P / 64, O / 128);
    gemm_db_k<<<g, 256>>>(W, bias, X, X2, addp, out, I, P, relu);
}

extern "C" void kernel_launch(void* const* d_in, const int* in_sizes, int n_in,
                              void* d_out, int out_size)
{
    const float* detections = (const float*)d_in[0];
    const float* tracks     = (const float*)d_in[1];
    const float* enc_w1 = (const float*)d_in[2];
    const float* enc_b1 = (const float*)d_in[3];
    const float* enc_w2 = (const float*)d_in[4];
    const float* enc_b2 = (const float*)d_in[5];
    const float* fus_pw  = (const float*)d_in[6];
    const float* fus_pb  = (const float*)d_in[7];
    const float* fus_mw  = (const float*)d_in[8];
    const float* fus_mb  = (const float*)d_in[9];
    const float* fus_m1w = (const float*)d_in[10];
    const float* fus_m1b = (const float*)d_in[11];
    const float* fus_m2w = (const float*)d_in[12];
    const float* fus_m2b = (const float*)d_in[13];
    const float* gnn_pw  = (const float*)d_in[14];
    const float* gnn_pb  = (const float*)d_in[15];
    const float* gnn_mw  = (const float*)d_in[16];
    const float* gnn_mb  = (const float*)d_in[17];
    const float* gnn_m1w = (const float*)d_in[18];
    const float* gnn_m1b = (const float*)d_in[19];
    const float* gnn_m2w = (const float*)d_in[20];
    const float* gnn_m2b = (const float*)d_in[21];
    const float* final_w = (const float*)d_in[22];
    const float* final_b = (const float*)d_in[23];
    const float* bin_score = (const float*)d_in[24];
    float* out = (float*)d_out;

    float* pool = nullptr;
    cudaGetSymbolAddress((void**)&pool, g_pool);
    size_t off = 0;
    auto carve = [&](size_t n) { float* p = pool + off; off += n; return p; };
    float* TRKIN = carve(4194304);
    float* DETIN = carve(1048576);
    float* TRKPE = carve(4194304);
    float* DETPE = carve(1048576);
    float* TMP1  = carve(8388608);
    float* QKV   = carve(12582912);
    float* MSG   = carve(4194304);
    float* MSG2  = carve(4194304);
    float* XA    = carve(4194304);
    float* XB    = carve(4194304);
    float* DETA  = carve(1048576);
    float* DETB  = carve(1048576);
    float* TRA   = carve(262144);
    float* TRB   = carve(262144);
    float* M0b   = carve(262144);
    float* M1b   = carve(1048576);
    float* Z0    = carve(1053700);
    float* U     = carve(1028);
    float* V     = carve(4100);
    float* CNT   = carve(4);

    // ---- gathers + PEs; order arranged so profiled launch slots 3 & 5 are
    //      representative P=16384 double-buffered GEMMs ----
    gather_trk<<<16384, 256>>>(tracks, TRKIN);     // 0
    gather_det<<<4096, 256>>>(detections, DETIN);  // 1
    pe_trk_k<<<16384, 256>>>(tracks, TRKPE);       // 2
    gemm(enc_w1, enc_b1, TRKIN, nullptr, nullptr, TMP1, 256, 256, P_TRK, 1);  // 3
    pe_det_k<<<4096, 256>>>(detections, DETPE);    // 4
    gemm(enc_w2, enc_b2, TMP1, nullptr, TRKPE, XA, 256, 256, P_TRK, 0);       // 5
    gemm(enc_w1, enc_b1, DETIN, nullptr, nullptr, TMP1, 256, 256, P_DET, 1);
    gemm(enc_w2, enc_b2, TMP1, nullptr, DETPE, DETA, 256, 256, P_DET, 0);

    // ---- fuser: 4 self-attention layers over T=16 ----
    float* x = XA; float* xo = XB;
    for (int l = 0; l < 4; l++) {
        const float* pw = fus_pw + l * 196608;
        const float* pb = fus_pb + l * 768;
        gemm(pw, pb, x, nullptr, nullptr, QKV, 768, 256, P_TRK, 0);  // fused QKV
        attn_k<<<dim3(1, 4, 1024), 64>>>(QKV, QKV + 256 * P_TRK, QKV + 512 * P_TRK,
                                         MSG, P_TRK, P_TRK, 16, 16);
        gemm(fus_mw + l * 65536, fus_mb + l * 256, MSG, nullptr, nullptr, MSG2,
             256, 256, P_TRK, 0);
        gemm(fus_m1w + l * 262144, fus_m1b + l * 512, x, MSG2, nullptr, TMP1,
             512, 512, P_TRK, 1);
        gemm(fus_m2w + l * 131072, fus_m2b + l * 256, TMP1, nullptr, x, xo,
             256, 512, P_TRK, 0);
        float* t = x; x = xo; xo = t;
    }
    pool_k<<<1024, 256>>>(x, TRA);

    // ---- GNN: 12 alternating self/cross layers ----
    float* tr = TRA; float* tro = TRB;
    float* de = DETA; float* deo = DETB;
    for (int l = 0; l < 12; l++) {
        const float* pw  = gnn_pw + l * 196608;
        const float* pb  = gnn_pb + l * 768;
        const float* mw  = gnn_mw + l * 65536;
        const float* mb  = gnn_mb + l * 256;
        const float* m1w = gnn_m1w + l * 262144;
        const float* m1b = gnn_m1b + l * 512;
        const float* m2w = gnn_m2w + l * 131072;
        const float* m2b = gnn_m2b + l * 256;
        int cross = l & 1;

        // d0: queries = tr
        if (!cross) {
            gemm(pw, pb, tr, nullptr, nullptr, QKV, 768, 256, P_TR, 0);
            attn_k<<<dim3(4, 4, 4), 64>>>(QKV, QKV + 256 * P_TR, QKV + 512 * P_TR,
                                          MSG, P_TR, P_TR, 256, 256);
        } else {
            gemm(pw, pb, tr, nullptr, nullptr, QKV, 256, 256, P_TR, 0);
            float* kvb = QKV + 256 * P_TR;
            gemm(pw + 65536, pb + 256, de, nullptr, nullptr, kvb, 512, 256, P_DET, 0);
            attn_k<<<dim3(4, 4, 4), 64>>>(QKV, kvb, kvb + 256 * P_DET,
                                          MSG, P_TR, P_DET, 256, 1024);
        }
        gemm(mw, mb, MSG, nullptr, nullptr, MSG2, 256, 256, P_TR, 0);
        gemm(m1w, m1b, tr, MSG2, nullptr, TMP1, 512, 512, P_TR, 1);
        gemm(m2w, m2b, TMP1, nullptr, tr, tro, 256, 512, P_TR, 0);

        // d1: queries = det (uses OLD tr)
        if (!cross) {
            gemm(pw, pb, de, nullptr, nullptr, QKV, 768, 256, P_DET, 0);
            attn_k<<<dim3(16, 4, 4), 64>>>(QKV, QKV + 256 * P_DET, QKV + 512 * P_DET,
                                           MSG, P_DET, P_DET, 1024, 1024);
        } else {
            gemm(pw, pb, de, nullptr, nullptr, QKV, 256, 256, P_DET, 0);
            float* kvb = QKV + 256 * P_DET;
            gemm(pw + 65536, pb + 256, tr, nullptr, nullptr, kvb, 512, 256, P_TR, 0);
            attn_k<<<dim3(16, 4, 4), 64>>>(QKV, kvb, kvb + 256 * P_TR,
                                           MSG, P_DET, P_TR, 1024, 256);
        }
        gemm(mw, mb, MSG, nullptr, nullptr, MSG2, 256, 256, P_DET, 0);
        gemm(m1w, m1b, de, MSG2, nullptr, TMP1, 512, 512, P_DET, 1);
        gemm(m2w, m2b, TMP1, nullptr, de, deo, 256, 512, P_DET, 0);

        float* t = tr; tr = tro; tro = t;
        t = de; de = deo; deo = t;
    }

    // ---- final projections + scores + Sinkhorn ----
    gemm(final_w, final_b, tr, nullptr, nullptr, M0b, 256, 256, P_TR, 0);
    gemm(final_w, final_b, de, nullptr, nullptr, M1b, 256, 256, P_DET, 0);
    scores_k<<<dim3(16, 4, 4), 256>>>(M0b, M1b, Z0);
    fill_bins<<<21, 256>>>(Z0, bin_score);
    zero_k<<<21, 256>>>(U, 5129);

    sink_fused_k<<<NBLK_SINK, 256>>>(Z0, U, V, (unsigned*)CNT);
    sink_out<<<(4 * ZROW + 255) / 256, 256>>>(Z0, U, V, out);
    (void)in_sizes; (void)n_in; (void)out_size;
}